// round 2
// baseline (speedup 1.0000x reference)
#include <cuda_runtime.h>
#include <cuda_bf16.h>

#define D 384
#define N_ETYPES 8
#define WARPS_PER_BLOCK 8
#define THREADS (WARPS_PER_BLOCK * 32)

__global__ __launch_bounds__(THREADS) void distmult_kernel(
    const float* __restrict__ h,
    const int* __restrict__ u,
    const int* __restrict__ v,
    const int* __restrict__ etype,
    const float* __restrict__ rel_weight,
    float* __restrict__ out,
    int n_edges)
{
    __shared__ float s_rel[N_ETYPES * D];  // 12 KB

    // Cooperative load of the tiny relation table into shared memory.
    for (int i = threadIdx.x; i < N_ETYPES * D; i += THREADS) {
        s_rel[i] = rel_weight[i];
    }
    __syncthreads();

    int gwarp = (blockIdx.x * THREADS + threadIdx.x) >> 5;
    int lane  = threadIdx.x & 31;
    if (gwarp >= n_edges) return;

    // Broadcast loads (all lanes same address -> single transaction).
    int ui = u[gwarp];
    int vi = v[gwarp];
    int ei = etype[gwarp];

    const float4* __restrict__ hu = (const float4*)(h + (size_t)ui * D);
    const float4* __restrict__ hv = (const float4*)(h + (size_t)vi * D);
    const float4* __restrict__ rr = (const float4*)(s_rel + ei * D);

    float acc = 0.0f;
#pragma unroll
    for (int i = 0; i < 3; i++) {
        int idx = lane + i * 32;        // 96 float4 per row, 3 per lane
        float4 a = hu[idx];
        float4 b = hv[idx];
        float4 c = rr[idx];
        acc = fmaf(a.x * c.x, b.x, acc);
        acc = fmaf(a.y * c.y, b.y, acc);
        acc = fmaf(a.z * c.z, b.z, acc);
        acc = fmaf(a.w * c.w, b.w, acc);
    }

    // Warp reduction.
#pragma unroll
    for (int off = 16; off > 0; off >>= 1)
        acc += __shfl_xor_sync(0xffffffffu, acc, off);

    if (lane == 0) {
        out[gwarp] = 1.0f / (1.0f + __expf(-acc));
    }
}

extern "C" void kernel_launch(void* const* d_in, const int* in_sizes, int n_in,
                              void* d_out, int out_size)
{
    const float* h   = (const float*)d_in[0];
    const int*   u   = (const int*)d_in[1];
    const int*   v   = (const int*)d_in[2];
    const int*   et  = (const int*)d_in[3];
    const float* rw  = (const float*)d_in[4];
    float*       out = (float*)d_out;

    int n_edges = in_sizes[1];  // E from u's element count

    int blocks = (n_edges + WARPS_PER_BLOCK - 1) / WARPS_PER_BLOCK;
    distmult_kernel<<<blocks, THREADS>>>(h, u, v, et, rw, out, n_edges);
}

// round 3
// speedup vs baseline: 1.1657x; 1.1657x over previous
#include <cuda_runtime.h>
#include <cuda_bf16.h>

#define D 384
#define N_ETYPES 8
#define THREADS 256
#define WARPS_PER_BLOCK (THREADS / 32)
#define EDGES_PER_WARP 32
#define FULL 0xffffffffu

__global__ __launch_bounds__(THREADS) void distmult_kernel(
    const float* __restrict__ h,
    const int* __restrict__ u,
    const int* __restrict__ v,
    const int* __restrict__ etype,
    const float* __restrict__ rel_weight,
    float* __restrict__ out,
    int n_edges)
{
    __shared__ float s_rel[N_ETYPES * D];  // 12 KB
    for (int i = threadIdx.x; i < N_ETYPES * D; i += THREADS)
        s_rel[i] = rel_weight[i];
    __syncthreads();

    int gwarp = (blockIdx.x * THREADS + threadIdx.x) >> 5;
    int lane  = threadIdx.x & 31;

    int base = gwarp * EDGES_PER_WARP;
    if (base >= n_edges) return;
    int n_here = min(EDGES_PER_WARP, n_edges - base);

    // Coalesced batch load of this warp's 32 edges' indices.
    int ue = 0, ve = 0, ee = 0;
    if (lane < n_here) {
        ue = u[base + lane];
        ve = v[base + lane];
        ee = etype[base + lane];
    }

    float my_out = 0.0f;

    for (int k = 0; k < n_here; k += 2) {
        int k1 = (k + 1 < n_here) ? (k + 1) : k;  // clamp (result discarded)

        int u0 = __shfl_sync(FULL, ue, k);
        int v0 = __shfl_sync(FULL, ve, k);
        int e0 = __shfl_sync(FULL, ee, k);
        int u1 = __shfl_sync(FULL, ue, k1);
        int v1 = __shfl_sync(FULL, ve, k1);
        int e1 = __shfl_sync(FULL, ee, k1);

        const float4* __restrict__ hu0 = (const float4*)(h + (size_t)u0 * D);
        const float4* __restrict__ hv0 = (const float4*)(h + (size_t)v0 * D);
        const float4* __restrict__ hu1 = (const float4*)(h + (size_t)u1 * D);
        const float4* __restrict__ hv1 = (const float4*)(h + (size_t)v1 * D);
        const float4* __restrict__ r0  = (const float4*)(s_rel + e0 * D);
        const float4* __restrict__ r1  = (const float4*)(s_rel + e1 * D);

        float acc0 = 0.0f, acc1 = 0.0f;
#pragma unroll
        for (int i = 0; i < 3; i++) {
            int idx = lane + i * 32;               // 96 float4 per row
            float4 a0 = __ldcg(hu0 + idx);         // skip L1, keep L2
            float4 b0 = __ldcg(hv0 + idx);
            float4 a1 = __ldcg(hu1 + idx);
            float4 b1 = __ldcg(hv1 + idx);
            float4 c0 = r0[idx];
            float4 c1 = r1[idx];
            acc0 = fmaf(a0.x * c0.x, b0.x, acc0);
            acc0 = fmaf(a0.y * c0.y, b0.y, acc0);
            acc0 = fmaf(a0.z * c0.z, b0.z, acc0);
            acc0 = fmaf(a0.w * c0.w, b0.w, acc0);
            acc1 = fmaf(a1.x * c1.x, b1.x, acc1);
            acc1 = fmaf(a1.y * c1.y, b1.y, acc1);
            acc1 = fmaf(a1.z * c1.z, b1.z, acc1);
            acc1 = fmaf(a1.w * c1.w, b1.w, acc1);
        }

        // Butterfly reductions (both edges).
#pragma unroll
        for (int off = 16; off > 0; off >>= 1) {
            acc0 += __shfl_xor_sync(FULL, acc0, off);
            acc1 += __shfl_xor_sync(FULL, acc1, off);
        }

        if (lane == k)      my_out = 1.0f / (1.0f + __expf(-acc0));
        if (lane == k + 1)  my_out = 1.0f / (1.0f + __expf(-acc1));
    }

    // Coalesced store: lane i holds edge base+i's score.
    if (lane < n_here)
        out[base + lane] = my_out;
}

extern "C" void kernel_launch(void* const* d_in, const int* in_sizes, int n_in,
                              void* d_out, int out_size)
{
    const float* h   = (const float*)d_in[0];
    const int*   u   = (const int*)d_in[1];
    const int*   v   = (const int*)d_in[2];
    const int*   et  = (const int*)d_in[3];
    const float* rw  = (const float*)d_in[4];
    float*       out = (float*)d_out;

    int n_edges = in_sizes[1];

    int warps  = (n_edges + EDGES_PER_WARP - 1) / EDGES_PER_WARP;
    int blocks = (warps + WARPS_PER_BLOCK - 1) / WARPS_PER_BLOCK;
    distmult_kernel<<<blocks, THREADS>>>(h, u, v, et, rw, out, n_edges);
}

// round 7
// speedup vs baseline: 1.3379x; 1.1477x over previous
#include <cuda_runtime.h>
#include <cuda_bf16.h>

#define D 384
#define N_ETYPES 8
#define THREADS 256
#define WARPS_PER_BLOCK (THREADS / 32)
#define EDGES_PER_WARP 32
#define FULL 0xffffffffu

__global__ __launch_bounds__(THREADS) void distmult_kernel(
    const float* __restrict__ h,
    const int* __restrict__ u,
    const int* __restrict__ v,
    const int* __restrict__ etype,
    const float* __restrict__ rel_weight,
    float* __restrict__ out,
    int n_edges)
{
    __shared__ float s_rel[N_ETYPES * D];  // 12 KB
    for (int i = threadIdx.x; i < N_ETYPES * D; i += THREADS)
        s_rel[i] = rel_weight[i];
    __syncthreads();

    int gwarp = (blockIdx.x * THREADS + threadIdx.x) >> 5;
    int lane  = threadIdx.x & 31;

    int base = gwarp * EDGES_PER_WARP;
    if (base >= n_edges) return;
    int n_here = min(EDGES_PER_WARP, n_edges - base);

    // Coalesced batch load of this warp's edges' indices (lane i -> edge base+i).
    int ue = 0, ve = 0, ee = 0;
    if (lane < n_here) {
        ue = u[base + lane];
        ve = v[base + lane];
        ee = etype[base + lane];
    }

    int g  = lane >> 3;   // group 0..3: which of 4 concurrent edges
    int gl = lane & 7;    // lane within group

    float my_out = 0.0f;

    int n_pass = (n_here + 3) >> 2;
    for (int k = 0; k < n_pass; k++) {
        // This group's edge for this pass (clamped for tail; result discarded).
        int eidx = min(4 * k + g, n_here - 1);
        int u0 = __shfl_sync(FULL, ue, eidx);
        int v0 = __shfl_sync(FULL, ve, eidx);
        int e0 = __shfl_sync(FULL, ee, eidx);

        const float4* __restrict__ hu = (const float4*)(h + (size_t)u0 * D);
        const float4* __restrict__ hv = (const float4*)(h + (size_t)v0 * D);
        const float4* __restrict__ rr = (const float4*)(s_rel + e0 * D);

        float acc = 0.0f;
#pragma unroll
        for (int i = 0; i < 12; i++) {          // 96 float4 per row / 8 lanes
            int idx = gl + i * 8;
            float4 a = __ldcg(hu + idx);        // bypass L1 (no reuse), keep L2
            float4 b = __ldcg(hv + idx);
            float4 c = rr[idx];
            acc = fmaf(a.x * c.x, b.x, acc);
            acc = fmaf(a.y * c.y, b.y, acc);
            acc = fmaf(a.z * c.z, b.z, acc);
            acc = fmaf(a.w * c.w, b.w, acc);
        }

        // Reduce within the 8-lane group (4 independent butterflies overlap).
        acc += __shfl_xor_sync(FULL, acc, 4);
        acc += __shfl_xor_sync(FULL, acc, 2);
        acc += __shfl_xor_sync(FULL, acc, 1);

        // Group g's total now replicated in lanes 8g..8g+7.
        // Owner lane (4k+g) fetches its result: src lane = 8*(lane - 4k).
        int src = (8 * (lane - 4 * k)) & 31;
        float r = __shfl_sync(FULL, acc, src);
        if ((lane >> 2) == k)
            my_out = 1.0f / (1.0f + __expf(-r));
    }

    // Coalesced store: lane i holds edge base+i's score.
    if (lane < n_here)
        out[base + lane] = my_out;
}

extern "C" void kernel_launch(void* const* d_in, const int* in_sizes, int n_in,
                              void* d_out, int out_size)
{
    const float* h   = (const float*)d_in[0];
    const int*   u   = (const int*)d_in[1];
    const int*   v   = (const int*)d_in[2];
    const int*   et  = (const int*)d_in[3];
    const float* rw  = (const float*)d_in[4];
    float*       out = (float*)d_out;

    int n_edges = in_sizes[1];

    int warps  = (n_edges + EDGES_PER_WARP - 1) / EDGES_PER_WARP;
    int blocks = (warps + WARPS_PER_BLOCK - 1) / WARPS_PER_BLOCK;
    distmult_kernel<<<blocks, THREADS>>>(h, u, v, et, rw, out, n_edges);
}

// round 9
// speedup vs baseline: 1.4511x; 1.0846x over previous
#include <cuda_runtime.h>
#include <cuda_bf16.h>

#define D 384
#define N_ETYPES 8
#define THREADS 256
#define WARPS_PER_BLOCK (THREADS / 32)
#define EDGES_PER_WARP 32
#define FULL 0xffffffffu

__global__ __launch_bounds__(THREADS, 3) void distmult_kernel(
    const float* __restrict__ h,
    const int* __restrict__ u,
    const int* __restrict__ v,
    const int* __restrict__ etype,
    const float* __restrict__ rel_weight,
    float* __restrict__ out,
    int n_edges)
{
    __shared__ float s_rel[N_ETYPES * D];  // 12 KB
    for (int i = threadIdx.x; i < N_ETYPES * D; i += THREADS)
        s_rel[i] = rel_weight[i];
    __syncthreads();

    int gwarp = (blockIdx.x * THREADS + threadIdx.x) >> 5;
    int lane  = threadIdx.x & 31;

    int base = gwarp * EDGES_PER_WARP;
    if (base >= n_edges) return;
    int n_here = min(EDGES_PER_WARP, n_edges - base);

    // Coalesced batch load of this warp's edges' indices (lane i -> edge base+i).
    int ue = 0, ve = 0, ee = 0;
    if (lane < n_here) {
        ue = u[base + lane];
        ve = v[base + lane];
        ee = etype[base + lane];
    }

    int g  = lane >> 3;   // group 0..3: which of 4 concurrent edges
    int gl = lane & 7;    // lane within group

    float my_out = 0.0f;

    int n_pass = (n_here + 3) >> 2;
    for (int k = 0; k < n_pass; k++) {
        // This group's edge for this pass (clamped for tail; result discarded).
        int eidx = min(4 * k + g, n_here - 1);
        int u0 = __shfl_sync(FULL, ue, eidx);
        int v0 = __shfl_sync(FULL, ve, eidx);
        int e0 = __shfl_sync(FULL, ee, eidx);

        const float4* __restrict__ hu = (const float4*)(h + (size_t)u0 * D);
        const float4* __restrict__ hv = (const float4*)(h + (size_t)v0 * D);
        const float4* __restrict__ rr = (const float4*)(s_rel + e0 * D);

        float acc = 0.0f;
#pragma unroll
        for (int c2 = 0; c2 < 2; c2++) {        // 2 chunks x 6 float4 per row
            float4 a[6], b[6];
            // Batch phase: 12 independent LDG.128 in flight before any use.
#pragma unroll
            for (int j = 0; j < 6; j++) {
                int idx = gl + (c2 * 6 + j) * 8;
                a[j] = __ldcg(hu + idx);        // bypass L1 (no reuse), keep L2
                b[j] = __ldcg(hv + idx);
            }
            // Consume phase.
#pragma unroll
            for (int j = 0; j < 6; j++) {
                int idx = gl + (c2 * 6 + j) * 8;
                float4 c = rr[idx];
                acc = fmaf(a[j].x * c.x, b[j].x, acc);
                acc = fmaf(a[j].y * c.y, b[j].y, acc);
                acc = fmaf(a[j].z * c.z, b[j].z, acc);
                acc = fmaf(a[j].w * c.w, b[j].w, acc);
            }
        }

        // Reduce within the 8-lane group (4 independent butterflies overlap).
        acc += __shfl_xor_sync(FULL, acc, 4);
        acc += __shfl_xor_sync(FULL, acc, 2);
        acc += __shfl_xor_sync(FULL, acc, 1);

        // Group g's total now replicated in lanes 8g..8g+7.
        // Owner lane (4k+g) fetches its result: src lane = 8*(lane - 4k).
        int src = (8 * (lane - 4 * k)) & 31;
        float r = __shfl_sync(FULL, acc, src);
        if ((lane >> 2) == k)
            my_out = 1.0f / (1.0f + __expf(-r));
    }

    // Coalesced store: lane i holds edge base+i's score.
    if (lane < n_here)
        out[base + lane] = my_out;
}

extern "C" void kernel_launch(void* const* d_in, const int* in_sizes, int n_in,
                              void* d_out, int out_size)
{
    const float* h   = (const float*)d_in[0];
    const int*   u   = (const int*)d_in[1];
    const int*   v   = (const int*)d_in[2];
    const int*   et  = (const int*)d_in[3];
    const float* rw  = (const float*)d_in[4];
    float*       out = (float*)d_out;

    int n_edges = in_sizes[1];

    int warps  = (n_edges + EDGES_PER_WARP - 1) / EDGES_PER_WARP;
    int blocks = (warps + WARPS_PER_BLOCK - 1) / WARPS_PER_BLOCK;
    distmult_kernel<<<blocks, THREADS>>>(h, u, v, et, rw, out, n_edges);
}

// round 14
// speedup vs baseline: 1.5244x; 1.0505x over previous
#include <cuda_runtime.h>
#include <cuda_bf16.h>

#define D 384
#define N_ETYPES 8
#define THREADS 256
#define WARPS_PER_BLOCK (THREADS / 32)
#define EDGES_PER_WARP 32
#define FULL 0xffffffffu

__global__ __launch_bounds__(THREADS, 4) void distmult_kernel(
    const float* __restrict__ h,
    const int* __restrict__ u,
    const int* __restrict__ v,
    const int* __restrict__ etype,
    const float* __restrict__ rel_weight,
    float* __restrict__ out,
    int n_edges)
{
    __shared__ float s_rel[N_ETYPES * D];  // 12 KB
    for (int i = threadIdx.x; i < N_ETYPES * D; i += THREADS)
        s_rel[i] = rel_weight[i];
    __syncthreads();

    int gwarp = (blockIdx.x * THREADS + threadIdx.x) >> 5;
    int lane  = threadIdx.x & 31;

    int base = gwarp * EDGES_PER_WARP;
    if (base >= n_edges) return;
    int n_here = min(EDGES_PER_WARP, n_edges - base);

    // Coalesced batch load of this warp's edges' indices (lane i -> edge base+i).
    int ue = 0, ve = 0, ee = 0;
    if (lane < n_here) {
        ue = u[base + lane];
        ve = v[base + lane];
        ee = etype[base + lane];
    }

    int g  = lane >> 3;   // group 0..3: which of 4 concurrent edges
    int gl = lane & 7;    // lane within group

    float my_out = 0.0f;

    int n_pass = (n_here + 3) >> 2;
    for (int k = 0; k < n_pass; k++) {
        // This group's edge for this pass (clamped for tail; result discarded).
        int eidx = min(4 * k + g, n_here - 1);
        int u0 = __shfl_sync(FULL, ue, eidx);
        int v0 = __shfl_sync(FULL, ve, eidx);
        int e0 = __shfl_sync(FULL, ee, eidx);

        const float4* __restrict__ hu = (const float4*)(h + (size_t)u0 * D);
        const float4* __restrict__ hv = (const float4*)(h + (size_t)v0 * D);
        const float4* __restrict__ rr = (const float4*)(s_rel + e0 * D);

        float acc = 0.0f;
#pragma unroll
        for (int c3 = 0; c3 < 3; c3++) {        // 3 chunks x 4 float4 per row
            float4 a[4], b[4];
            // Batch phase: 8 independent LDG.128 in flight before any use.
#pragma unroll
            for (int j = 0; j < 4; j++) {
                int idx = gl + (c3 * 4 + j) * 8;
                a[j] = __ldcg(hu + idx);        // bypass L1 (no reuse), keep L2
                b[j] = __ldcg(hv + idx);
            }
            // Consume phase.
#pragma unroll
            for (int j = 0; j < 4; j++) {
                int idx = gl + (c3 * 4 + j) * 8;
                float4 c = rr[idx];
                acc = fmaf(a[j].x * c.x, b[j].x, acc);
                acc = fmaf(a[j].y * c.y, b[j].y, acc);
                acc = fmaf(a[j].z * c.z, b[j].z, acc);
                acc = fmaf(a[j].w * c.w, b[j].w, acc);
            }
        }

        // Reduce within the 8-lane group (4 independent butterflies overlap).
        acc += __shfl_xor_sync(FULL, acc, 4);
        acc += __shfl_xor_sync(FULL, acc, 2);
        acc += __shfl_xor_sync(FULL, acc, 1);

        // Group g's total now replicated in lanes 8g..8g+7.
        // Owner lane (4k+g) fetches its result: src lane = 8*(lane - 4k).
        int src = (8 * (lane - 4 * k)) & 31;
        float r = __shfl_sync(FULL, acc, src);
        if ((lane >> 2) == k)
            my_out = 1.0f / (1.0f + __expf(-r));
    }

    // Coalesced store: lane i holds edge base+i's score.
    if (lane < n_here)
        out[base + lane] = my_out;
}

extern "C" void kernel_launch(void* const* d_in, const int* in_sizes, int n_in,
                              void* d_out, int out_size)
{
    const float* h   = (const float*)d_in[0];
    const int*   u   = (const int*)d_in[1];
    const int*   v   = (const int*)d_in[2];
    const int*   et  = (const int*)d_in[3];
    const float* rw  = (const float*)d_in[4];
    float*       out = (float*)d_out;

    int n_edges = in_sizes[1];

    int warps  = (n_edges + EDGES_PER_WARP - 1) / EDGES_PER_WARP;
    int blocks = (warps + WARPS_PER_BLOCK - 1) / WARPS_PER_BLOCK;
    distmult_kernel<<<blocks, THREADS>>>(h, u, v, et, rw, out, n_edges);
}